// round 12
// baseline (speedup 1.0000x reference)
#include <cuda_runtime.h>
#include <cstdint>

#define NNODES 40000
#define INDIM  128
#define HID    64
#define NEDGES 640000
#define SLOT_SHIFT 7           // 128 slots per node (P(deg>128) ~ 0 for E/N=16)

typedef unsigned long long ull;

// ---------------- scratch (device globals) ----------------
__device__ float g_y[NNODES * HID];       // lin_l(x) per node
__device__ float g_r[NNODES * HID];       // lin_r(x) per node
__device__ float g_h[NNODES * HID];       // layer-1 activation
__device__ int   g_deg[NNODES];           // zero-init; re-zeroed by pull2 each call
__device__ int   g_csr[NNODES << SLOT_SHIFT];  // slot table: src ids per dst

// ---------------- fused CSR build: count + slot scatter ----------------
__global__ void k_build(const int* __restrict__ ei) {
    int i = blockIdx.x * blockDim.x + threadIdx.x;
    if (i >= NEDGES / 4) return;
    int4 s = ((const int4*)ei)[i];
    int4 d = ((const int4*)(ei + NEDGES))[i];
    int r;
    r = atomicAdd(&g_deg[d.x], 1); g_csr[(d.x << SLOT_SHIFT) + r] = s.x;
    r = atomicAdd(&g_deg[d.y], 1); g_csr[(d.y << SLOT_SHIFT) + r] = s.y;
    r = atomicAdd(&g_deg[d.z], 1); g_csr[(d.z << SLOT_SHIFT) + r] = s.z;
    r = atomicAdd(&g_deg[d.w], 1); g_csr[(d.w << SLOT_SHIFT) + r] = s.w;
}

// ---------------- dual GEMM: [Y|R] = X @ [Wl|Wr]^T ----------------
// Block: 64 rows x 128 k, 256 threads. Thread: 4 k x 8 rows (4 f32x2 pairs).
template <int KI, bool FROMH>
__global__ __launch_bounds__(256, 4) void k_gemm_dual(
    const float* __restrict__ Xin, const float* __restrict__ Wl,
    const float* __restrict__ Wr) {
    __shared__ float Ws[32][132];  // [d][k]
    __shared__ float Xs[32][66];   // [d][row]

    const float* __restrict__ X = FROMH ? (const float*)g_h : Xin;

    const int t  = threadIdx.x;
    const int tc = t & 31;
    const int tw = t >> 5;
    const int k0 = tc << 2;
    const int r0 = tw << 3;
    const int rowBase = blockIdx.x << 6;

    ull acc[4][4];
#pragma unroll
    for (int a = 0; a < 4; a++)
#pragma unroll
        for (int b = 0; b < 4; b++) acc[a][b] = 0ULL;

    const int kw    = t >> 1;
    const int partW = t & 1;
    const float* __restrict__ Wg =
        (kw < HID) ? (Wl + (size_t)kw * KI) : (Wr + (size_t)(kw - HID) * KI);
    const int lrow  = t >> 2;
    const int partX = t & 3;
    const float* __restrict__ Xg =
        X + (size_t)(rowBase + lrow) * KI + partX * 8;

#pragma unroll 1
    for (int d0 = 0; d0 < KI; d0 += 32) {
#pragma unroll
        for (int j = 0; j < 4; j++) {
            float4 w = *(const float4*)(Wg + d0 + partW * 16 + j * 4);
            int dd = partW * 16 + j * 4;
            Ws[dd + 0][kw] = w.x; Ws[dd + 1][kw] = w.y;
            Ws[dd + 2][kw] = w.z; Ws[dd + 3][kw] = w.w;
        }
#pragma unroll
        for (int j = 0; j < 2; j++) {
            float4 v = *(const float4*)(Xg + d0 + j * 4);
            int dd = partX * 8 + j * 4;
            Xs[dd + 0][lrow] = v.x; Xs[dd + 1][lrow] = v.y;
            Xs[dd + 2][lrow] = v.z; Xs[dd + 3][lrow] = v.w;
        }
        __syncthreads();

#pragma unroll
        for (int d = 0; d < 32; d++) {
            float4 wv = *(const float4*)&Ws[d][k0];
            ull w2[4];
            unsigned int wu;
            wu = __float_as_uint(wv.x); asm("mov.b64 %0, {%1,%1};" : "=l"(w2[0]) : "r"(wu));
            wu = __float_as_uint(wv.y); asm("mov.b64 %0, {%1,%1};" : "=l"(w2[1]) : "r"(wu));
            wu = __float_as_uint(wv.z); asm("mov.b64 %0, {%1,%1};" : "=l"(w2[2]) : "r"(wu));
            wu = __float_as_uint(wv.w); asm("mov.b64 %0, {%1,%1};" : "=l"(w2[3]) : "r"(wu));
#pragma unroll
            for (int j = 0; j < 4; j++) {
                ull xp = *(const ull*)&Xs[d][r0 + 2 * j];
#pragma unroll
                for (int kk = 0; kk < 4; kk++)
                    asm("fma.rn.f32x2 %0, %1, %2, %0;"
                        : "+l"(acc[kk][j]) : "l"(w2[kk]), "l"(xp));
            }
        }
        __syncthreads();
    }

    float* __restrict__ Obase = (k0 < HID) ? (g_y + k0) : (g_r + (k0 - HID));
#pragma unroll
    for (int j = 0; j < 4; j++) {
        int row = rowBase + r0 + 2 * j;
        float2 f[4];
#pragma unroll
        for (int kk = 0; kk < 4; kk++) f[kk] = *(float2*)&acc[kk][j];
        float4 lo = make_float4(f[0].x, f[1].x, f[2].x, f[3].x);
        float4 hi = make_float4(f[0].y, f[1].y, f[2].y, f[3].y);
        *(float4*)(Obase + (size_t)row * HID) = lo;
        *(float4*)(Obase + (size_t)(row + 1) * HID) = hi;
    }
}

// ---------------- pull aggregation fused with epilogue ----------------
// One warp per dst node, split into 2 half-warps: lanes 0-15 take even
// ranks, 16-31 odd ranks; each lane holds float4 (16 lanes = 256B row).
// Halves combined with one shfl_xor(16). ZERODEG: restore g_deg=0 (pull2).
template <bool RELU, bool TOH, bool ZERODEG>
__global__ __launch_bounds__(256) void k_pull(
    const float* __restrict__ bias, float* __restrict__ outp) {
    int w = (blockIdx.x * blockDim.x + threadIdx.x) >> 5;
    int lane = threadIdx.x & 31;
    if (w >= NNODES) return;

    const int deg  = g_deg[w];                 // broadcast load
    const int half = lane >> 4;                // 0 or 1
    const int hl   = lane & 15;                // channel group
    const int base = w << SLOT_SHIFT;

    float4 acc = make_float4(0.f, 0.f, 0.f, 0.f);
#pragma unroll 2
    for (int j = half; j < deg; j += 2) {
        int s = g_csr[base + j];               // same addr across half: broadcast
        float4 v = *(const float4*)(g_y + (size_t)s * HID + hl * 4);
        acc.x += v.x; acc.y += v.y; acc.z += v.z; acc.w += v.w;
    }
    // combine even/odd halves (same channels, different neighbors)
    acc.x += __shfl_xor_sync(0xffffffffu, acc.x, 16);
    acc.y += __shfl_xor_sync(0xffffffffu, acc.y, 16);
    acc.z += __shfl_xor_sync(0xffffffffu, acc.z, 16);
    acc.w += __shfl_xor_sync(0xffffffffu, acc.w, 16);

    if (ZERODEG && lane == 0) g_deg[w] = 0;    // restore invariant

    if (half == 0) {
        float inv = 1.0f / fmaxf((float)deg, 1.0f);
        float4 r = *(const float4*)(g_r + (size_t)w * HID + hl * 4);
        float4 b = *(const float4*)(bias + hl * 4);
        float4 o;
        o.x = fmaf(acc.x, inv, r.x + b.x);
        o.y = fmaf(acc.y, inv, r.y + b.y);
        o.z = fmaf(acc.z, inv, r.z + b.z);
        o.w = fmaf(acc.w, inv, r.w + b.w);
        if (RELU) {
            o.x = fmaxf(o.x, 0.f); o.y = fmaxf(o.y, 0.f);
            o.z = fmaxf(o.z, 0.f); o.w = fmaxf(o.w, 0.f);
        }
        float* dstp = TOH ? (g_h + (size_t)w * HID + hl * 4)
                          : (outp + (size_t)w * HID + hl * 4);
        *(float4*)dstp = o;
    }
}

// ---------------- launch: build on side stream ∥ GEMM1 on main --------
extern "C" void kernel_launch(void* const* d_in, const int* in_sizes, int n_in,
                              void* d_out, int out_size) {
    const float* x   = (const float*)d_in[0];
    const int*   ei  = (const int*)d_in[1];
    const float* W1l = (const float*)d_in[2];
    const float* b1  = (const float*)d_in[3];
    const float* W1r = (const float*)d_in[4];
    const float* W2l = (const float*)d_in[5];
    const float* b2  = (const float*)d_in[6];
    const float* W2r = (const float*)d_in[7];
    float* out = (float*)d_out;

    const int gGemm = NNODES / 64;                 // 625
    const int gPull = (NNODES * 32 + 255) / 256;   // 5000
    const int gE4   = (NEDGES / 4 + 255) / 256;    // 625

    static cudaStream_t s2 = nullptr;
    static cudaEvent_t  eFork = nullptr, eJoin = nullptr;
    static bool forked = false;
    if (!s2) {
        if (cudaStreamCreateWithFlags(&s2, cudaStreamNonBlocking) == cudaSuccess &&
            cudaEventCreateWithFlags(&eFork, cudaEventDisableTiming) == cudaSuccess &&
            cudaEventCreateWithFlags(&eJoin, cudaEventDisableTiming) == cudaSuccess)
            forked = true;
    }

    if (forked) {
        cudaEventRecord(eFork, 0);
        cudaStreamWaitEvent(s2, eFork, 0);
        k_build<<<gE4, 256, 0, s2>>>(ei);
        cudaEventRecord(eJoin, s2);

        k_gemm_dual<INDIM, false><<<gGemm, 256>>>(x, W1l, W1r);

        cudaStreamWaitEvent(0, eJoin, 0);
    } else {
        k_build<<<gE4, 256>>>(ei);
        k_gemm_dual<INDIM, false><<<gGemm, 256>>>(x, W1l, W1r);
    }

    // layer 1 aggregate + epilogue
    k_pull<true, true, false><<<gPull, 256>>>(b1, nullptr);

    // layer 2
    k_gemm_dual<HID, true><<<gGemm, 256>>>(nullptr, W2l, W2r);
    k_pull<false, false, true><<<gPull, 256>>>(b2, out);
}

// round 13
// speedup vs baseline: 1.2858x; 1.2858x over previous
#include <cuda_runtime.h>
#include <cstdint>

#define NNODES 40000
#define INDIM  128
#define HID    64
#define NEDGES 640000
#define SLOT_SHIFT 7           // 128 slots per node (P(deg>128) ~ 0 for E/N=16)
#define NTILES (NNODES / 64)   // 625

typedef unsigned long long ull;

// ---------------- scratch (device globals) ----------------
__device__ float g_y[NNODES * HID];       // lin_l(x) per node
__device__ float g_r[NNODES * HID];       // lin_r(x) per node
__device__ float g_h[NNODES * HID];       // layer-1 activation
__device__ int   g_deg[NNODES];           // zero-init; re-zeroed by pull2 each call
__device__ int   g_csr[NNODES << SLOT_SHIFT];  // slot table: src ids per dst

// ---------------- fused CSR build: count + slot scatter ----------------
__global__ void k_build(const int* __restrict__ ei) {
    int i = blockIdx.x * blockDim.x + threadIdx.x;
    if (i >= NEDGES / 4) return;
    int4 s = ((const int4*)ei)[i];
    int4 d = ((const int4*)(ei + NEDGES))[i];
    int r;
    r = atomicAdd(&g_deg[d.x], 1); g_csr[(d.x << SLOT_SHIFT) + r] = s.x;
    r = atomicAdd(&g_deg[d.y], 1); g_csr[(d.y << SLOT_SHIFT) + r] = s.y;
    r = atomicAdd(&g_deg[d.z], 1); g_csr[(d.z << SLOT_SHIFT) + r] = s.z;
    r = atomicAdd(&g_deg[d.w], 1); g_csr[(d.w << SLOT_SHIFT) + r] = s.w;
}

// ---------------- dual GEMM: [Y|R] = X @ [Wl|Wr]^T ----------------
// Tile: 64 rows x 128 k, 256 threads, d0-chunk 16 (smem 12.7KB), 3 blocks/SM,
// 2 row-tiles per block (grid 313). Thread: 4 k x 8 rows (f32x2 pairs).
template <int KI, bool FROMH>
__global__ __launch_bounds__(256, 3) void k_gemm_dual(
    const float* __restrict__ Xin, const float* __restrict__ Wl,
    const float* __restrict__ Wr) {
    __shared__ float Ws[16][132];  // [d][k]
    __shared__ float Xs[16][66];   // [d][row]

    const float* __restrict__ X = FROMH ? (const float*)g_h : Xin;

    const int t  = threadIdx.x;
    const int tc = t & 31;
    const int tw = t >> 5;
    const int k0 = tc << 2;
    const int r0 = tw << 3;

    const int kw    = t >> 1;         // weight row 0..127
    const int partW = t & 1;
    const float* __restrict__ Wg =
        (kw < HID) ? (Wl + (size_t)kw * KI) : (Wr + (size_t)(kw - HID) * KI);
    const int lrow  = t >> 2;         // X row 0..63
    const int partX = t & 3;

    float* __restrict__ Obase = (k0 < HID) ? (g_y + k0) : (g_r + (k0 - HID));

    for (int tile = blockIdx.x; tile < NTILES; tile += gridDim.x) {
        const int rowBase = tile << 6;
        const float* __restrict__ Xg =
            X + (size_t)(rowBase + lrow) * KI + partX * 4;

        ull acc[4][4];
#pragma unroll
        for (int a = 0; a < 4; a++)
#pragma unroll
            for (int b = 0; b < 4; b++) acc[a][b] = 0ULL;

#pragma unroll 1
        for (int d0 = 0; d0 < KI; d0 += 16) {
            // stage W chunk transposed: Ws[d][k]  (2 float4 per thread)
#pragma unroll
            for (int j = 0; j < 2; j++) {
                float4 w = *(const float4*)(Wg + d0 + partW * 8 + j * 4);
                int dd = partW * 8 + j * 4;
                Ws[dd + 0][kw] = w.x; Ws[dd + 1][kw] = w.y;
                Ws[dd + 2][kw] = w.z; Ws[dd + 3][kw] = w.w;
            }
            // stage X chunk transposed: Xs[d][row] (1 float4 per thread)
            {
                float4 v = *(const float4*)(Xg + d0);
                int dd = partX * 4;
                Xs[dd + 0][lrow] = v.x; Xs[dd + 1][lrow] = v.y;
                Xs[dd + 2][lrow] = v.z; Xs[dd + 3][lrow] = v.w;
            }
            __syncthreads();

#pragma unroll
            for (int d = 0; d < 16; d++) {
                float4 wv = *(const float4*)&Ws[d][k0];
                ull w2[4];
                unsigned int wu;
                wu = __float_as_uint(wv.x); asm("mov.b64 %0, {%1,%1};" : "=l"(w2[0]) : "r"(wu));
                wu = __float_as_uint(wv.y); asm("mov.b64 %0, {%1,%1};" : "=l"(w2[1]) : "r"(wu));
                wu = __float_as_uint(wv.z); asm("mov.b64 %0, {%1,%1};" : "=l"(w2[2]) : "r"(wu));
                wu = __float_as_uint(wv.w); asm("mov.b64 %0, {%1,%1};" : "=l"(w2[3]) : "r"(wu));
#pragma unroll
                for (int j = 0; j < 4; j++) {
                    ull xp = *(const ull*)&Xs[d][r0 + 2 * j];
#pragma unroll
                    for (int kk = 0; kk < 4; kk++)
                        asm("fma.rn.f32x2 %0, %1, %2, %0;"
                            : "+l"(acc[kk][j]) : "l"(w2[kk]), "l"(xp));
                }
            }
            __syncthreads();
        }

        // epilogue: 4k x 8 rows
#pragma unroll
        for (int j = 0; j < 4; j++) {
            int row = rowBase + r0 + 2 * j;
            float2 f[4];
#pragma unroll
            for (int kk = 0; kk < 4; kk++) f[kk] = *(float2*)&acc[kk][j];
            float4 lo = make_float4(f[0].x, f[1].x, f[2].x, f[3].x);
            float4 hi = make_float4(f[0].y, f[1].y, f[2].y, f[3].y);
            *(float4*)(Obase + (size_t)row * HID) = lo;
            *(float4*)(Obase + (size_t)(row + 1) * HID) = hi;
        }
    }
}

// ---------------- pull aggregation fused with epilogue ----------------
// One warp per dst node (shfl-broadcast over slot table):
// out = mean(y[neighbors]) + bias + r  [+ relu]
template <bool RELU, bool TOH, bool ZERODEG>
__global__ __launch_bounds__(256) void k_pull(
    const float* __restrict__ bias, float* __restrict__ outp) {
    int w = (blockIdx.x * blockDim.x + threadIdx.x) >> 5;
    int lane = threadIdx.x & 31;
    if (w >= NNODES) return;

    const int deg = g_deg[w];
    const int beg = w << SLOT_SHIFT;
    float2 acc = make_float2(0.f, 0.f);

    for (int base = 0; base < deg; base += 32) {
        int idx = base + lane;
        int my = (idx < deg) ? g_csr[beg + idx] : 0;   // coalesced slot row
        int m = min(32, deg - base);
#pragma unroll 4
        for (int j = 0; j < m; j++) {
            int s = __shfl_sync(0xffffffffu, my, j);
            float2 v = *(const float2*)(g_y + (size_t)s * HID + lane * 2);
            acc.x += v.x; acc.y += v.y;
        }
    }

    if (ZERODEG && lane == 0) g_deg[w] = 0;   // restore invariant (after reads)

    float inv = 1.0f / fmaxf((float)deg, 1.0f);
    float2 r = *(const float2*)(g_r + (size_t)w * HID + lane * 2);
    float2 b = *(const float2*)(bias + lane * 2);
    float2 o;
    o.x = fmaf(acc.x, inv, r.x + b.x);
    o.y = fmaf(acc.y, inv, r.y + b.y);
    if (RELU) { o.x = fmaxf(o.x, 0.f); o.y = fmaxf(o.y, 0.f); }
    float* dstp = TOH ? (g_h + (size_t)w * HID + lane * 2)
                      : (outp + (size_t)w * HID + lane * 2);
    *(float2*)dstp = o;
}

// ---------------- launch: build on side stream ∥ GEMM1 on main --------
extern "C" void kernel_launch(void* const* d_in, const int* in_sizes, int n_in,
                              void* d_out, int out_size) {
    const float* x   = (const float*)d_in[0];
    const int*   ei  = (const int*)d_in[1];
    const float* W1l = (const float*)d_in[2];
    const float* b1  = (const float*)d_in[3];
    const float* W1r = (const float*)d_in[4];
    const float* W2l = (const float*)d_in[5];
    const float* b2  = (const float*)d_in[6];
    const float* W2r = (const float*)d_in[7];
    float* out = (float*)d_out;

    const int gGemm = 313;                         // 2 row-tiles per block
    const int gPull = (NNODES * 32 + 255) / 256;   // 5000
    const int gE4   = (NEDGES / 4 + 255) / 256;    // 625

    static cudaStream_t s2 = nullptr;
    static cudaEvent_t  eFork = nullptr, eJoin = nullptr;
    static bool forked = false;
    if (!s2) {
        if (cudaStreamCreateWithFlags(&s2, cudaStreamNonBlocking) == cudaSuccess &&
            cudaEventCreateWithFlags(&eFork, cudaEventDisableTiming) == cudaSuccess &&
            cudaEventCreateWithFlags(&eJoin, cudaEventDisableTiming) == cudaSuccess)
            forked = true;
    }

    if (forked) {
        cudaEventRecord(eFork, 0);
        cudaStreamWaitEvent(s2, eFork, 0);
        k_build<<<gE4, 256, 0, s2>>>(ei);
        cudaEventRecord(eJoin, s2);

        k_gemm_dual<INDIM, false><<<gGemm, 256>>>(x, W1l, W1r);

        cudaStreamWaitEvent(0, eJoin, 0);
    } else {
        k_build<<<gE4, 256>>>(ei);
        k_gemm_dual<INDIM, false><<<gGemm, 256>>>(x, W1l, W1r);
    }

    // layer 1 aggregate + epilogue
    k_pull<true, true, false><<<gPull, 256>>>(b1, nullptr);

    // layer 2
    k_gemm_dual<HID, true><<<gGemm, 256>>>(nullptr, W2l, W2r);
    k_pull<false, false, true><<<gPull, 256>>>(b2, out);
}

// round 14
// speedup vs baseline: 1.4637x; 1.1384x over previous
#include <cuda_runtime.h>
#include <cstdint>

#define NNODES 40000
#define INDIM  128
#define HID    64
#define NEDGES 640000
#define SLOT_SHIFT 7           // 128 slots per node (P(deg>128) ~ 0 for E/N=16)

typedef unsigned long long ull;

// ---------------- scratch (device globals) ----------------
__device__ float g_y[NNODES * HID];       // lin_l(x) per node
__device__ float g_r[NNODES * HID];       // lin_r(x) per node
__device__ float g_h[NNODES * HID];       // layer-1 activation
__device__ int   g_deg[NNODES];           // zero-init; re-zeroed by pull2 each call
__device__ int   g_csr[NNODES << SLOT_SHIFT];  // slot table: src ids per dst

// ---------------- fused CSR build: count + slot scatter ----------------
__global__ void k_build(const int* __restrict__ ei) {
    int i = blockIdx.x * blockDim.x + threadIdx.x;
    if (i >= NEDGES / 4) return;
    int4 s = ((const int4*)ei)[i];
    int4 d = ((const int4*)(ei + NEDGES))[i];
    int r;
    r = atomicAdd(&g_deg[d.x], 1); g_csr[(d.x << SLOT_SHIFT) + r] = s.x;
    r = atomicAdd(&g_deg[d.y], 1); g_csr[(d.y << SLOT_SHIFT) + r] = s.y;
    r = atomicAdd(&g_deg[d.z], 1); g_csr[(d.z << SLOT_SHIFT) + r] = s.z;
    r = atomicAdd(&g_deg[d.w], 1); g_csr[(d.w << SLOT_SHIFT) + r] = s.w;
}

// ---------------- dual GEMM: [Y|R] = X @ [Wl|Wr]^T ----------------
// Tile: 64 rows x 128 k, 256 threads, d0-chunk 32 (smem 25.3KB), 3 blocks/SM,
// grid 625 (1 tile/block). Thread: 4 k x 8 rows (4 f32x2 pairs).
template <int KI, bool FROMH>
__global__ __launch_bounds__(256, 3) void k_gemm_dual(
    const float* __restrict__ Xin, const float* __restrict__ Wl,
    const float* __restrict__ Wr) {
    __shared__ float Ws[32][132];  // [d][k]
    __shared__ float Xs[32][66];   // [d][row]

    const float* __restrict__ X = FROMH ? (const float*)g_h : Xin;

    const int t  = threadIdx.x;
    const int tc = t & 31;
    const int tw = t >> 5;
    const int k0 = tc << 2;
    const int r0 = tw << 3;
    const int rowBase = blockIdx.x << 6;

    ull acc[4][4];
#pragma unroll
    for (int a = 0; a < 4; a++)
#pragma unroll
        for (int b = 0; b < 4; b++) acc[a][b] = 0ULL;

    const int kw    = t >> 1;         // weight row 0..127
    const int partW = t & 1;
    const float* __restrict__ Wg =
        (kw < HID) ? (Wl + (size_t)kw * KI) : (Wr + (size_t)(kw - HID) * KI);
    const int lrow  = t >> 2;         // X row 0..63
    const int partX = t & 3;
    const float* __restrict__ Xg =
        X + (size_t)(rowBase + lrow) * KI + partX * 8;

#pragma unroll 1
    for (int d0 = 0; d0 < KI; d0 += 32) {
#pragma unroll
        for (int j = 0; j < 4; j++) {
            float4 w = *(const float4*)(Wg + d0 + partW * 16 + j * 4);
            int dd = partW * 16 + j * 4;
            Ws[dd + 0][kw] = w.x; Ws[dd + 1][kw] = w.y;
            Ws[dd + 2][kw] = w.z; Ws[dd + 3][kw] = w.w;
        }
#pragma unroll
        for (int j = 0; j < 2; j++) {
            float4 v = *(const float4*)(Xg + d0 + j * 4);
            int dd = partX * 8 + j * 4;
            Xs[dd + 0][lrow] = v.x; Xs[dd + 1][lrow] = v.y;
            Xs[dd + 2][lrow] = v.z; Xs[dd + 3][lrow] = v.w;
        }
        __syncthreads();

#pragma unroll
        for (int d = 0; d < 32; d++) {
            float4 wv = *(const float4*)&Ws[d][k0];
            ull w2[4];
            unsigned int wu;
            wu = __float_as_uint(wv.x); asm("mov.b64 %0, {%1,%1};" : "=l"(w2[0]) : "r"(wu));
            wu = __float_as_uint(wv.y); asm("mov.b64 %0, {%1,%1};" : "=l"(w2[1]) : "r"(wu));
            wu = __float_as_uint(wv.z); asm("mov.b64 %0, {%1,%1};" : "=l"(w2[2]) : "r"(wu));
            wu = __float_as_uint(wv.w); asm("mov.b64 %0, {%1,%1};" : "=l"(w2[3]) : "r"(wu));
#pragma unroll
            for (int j = 0; j < 4; j++) {
                ull xp = *(const ull*)&Xs[d][r0 + 2 * j];
#pragma unroll
                for (int kk = 0; kk < 4; kk++)
                    asm("fma.rn.f32x2 %0, %1, %2, %0;"
                        : "+l"(acc[kk][j]) : "l"(w2[kk]), "l"(xp));
            }
        }
        __syncthreads();
    }

    float* __restrict__ Obase = (k0 < HID) ? (g_y + k0) : (g_r + (k0 - HID));
#pragma unroll
    for (int j = 0; j < 4; j++) {
        int row = rowBase + r0 + 2 * j;
        float2 f[4];
#pragma unroll
        for (int kk = 0; kk < 4; kk++) f[kk] = *(float2*)&acc[kk][j];
        float4 lo = make_float4(f[0].x, f[1].x, f[2].x, f[3].x);
        float4 hi = make_float4(f[0].y, f[1].y, f[2].y, f[3].y);
        *(float4*)(Obase + (size_t)row * HID) = lo;
        *(float4*)(Obase + (size_t)(row + 1) * HID) = hi;
    }
}

// ---------------- pull aggregation fused with epilogue ----------------
// One warp per dst node (shfl-broadcast over slot table):
// out = mean(y[neighbors]) + bias + r  [+ relu]
template <bool RELU, bool TOH, bool ZERODEG>
__global__ __launch_bounds__(256) void k_pull(
    const float* __restrict__ bias, float* __restrict__ outp) {
    int w = (blockIdx.x * blockDim.x + threadIdx.x) >> 5;
    int lane = threadIdx.x & 31;
    if (w >= NNODES) return;

    const int deg = g_deg[w];
    const int beg = w << SLOT_SHIFT;
    float2 acc = make_float2(0.f, 0.f);

    for (int base = 0; base < deg; base += 32) {
        int idx = base + lane;
        int my = (idx < deg) ? g_csr[beg + idx] : 0;   // coalesced slot row
        int m = min(32, deg - base);
#pragma unroll 4
        for (int j = 0; j < m; j++) {
            int s = __shfl_sync(0xffffffffu, my, j);
            float2 v = *(const float2*)(g_y + (size_t)s * HID + lane * 2);
            acc.x += v.x; acc.y += v.y;
        }
    }

    if (ZERODEG && lane == 0) g_deg[w] = 0;   // restore invariant (after reads)

    float inv = 1.0f / fmaxf((float)deg, 1.0f);
    float2 r = *(const float2*)(g_r + (size_t)w * HID + lane * 2);
    float2 b = *(const float2*)(bias + lane * 2);
    float2 o;
    o.x = fmaf(acc.x, inv, r.x + b.x);
    o.y = fmaf(acc.y, inv, r.y + b.y);
    if (RELU) { o.x = fmaxf(o.x, 0.f); o.y = fmaxf(o.y, 0.f); }
    float* dstp = TOH ? (g_h + (size_t)w * HID + lane * 2)
                      : (outp + (size_t)w * HID + lane * 2);
    *(float2*)dstp = o;
}

// ---------------- launch: build on side stream ∥ GEMM1 on main --------
extern "C" void kernel_launch(void* const* d_in, const int* in_sizes, int n_in,
                              void* d_out, int out_size) {
    const float* x   = (const float*)d_in[0];
    const int*   ei  = (const int*)d_in[1];
    const float* W1l = (const float*)d_in[2];
    const float* b1  = (const float*)d_in[3];
    const float* W1r = (const float*)d_in[4];
    const float* W2l = (const float*)d_in[5];
    const float* b2  = (const float*)d_in[6];
    const float* W2r = (const float*)d_in[7];
    float* out = (float*)d_out;

    const int gGemm = NNODES / 64;                 // 625 (1 tile per block)
    const int gPull = (NNODES * 32 + 255) / 256;   // 5000
    const int gE4   = (NEDGES / 4 + 255) / 256;    // 625

    static cudaStream_t s2 = nullptr;
    static cudaEvent_t  eFork = nullptr, eJoin = nullptr;
    static bool forked = false;
    if (!s2) {
        if (cudaStreamCreateWithFlags(&s2, cudaStreamNonBlocking) == cudaSuccess &&
            cudaEventCreateWithFlags(&eFork, cudaEventDisableTiming) == cudaSuccess &&
            cudaEventCreateWithFlags(&eJoin, cudaEventDisableTiming) == cudaSuccess)
            forked = true;
    }

    if (forked) {
        cudaEventRecord(eFork, 0);
        cudaStreamWaitEvent(s2, eFork, 0);
        k_build<<<gE4, 256, 0, s2>>>(ei);
        cudaEventRecord(eJoin, s2);

        k_gemm_dual<INDIM, false><<<gGemm, 256>>>(x, W1l, W1r);

        cudaStreamWaitEvent(0, eJoin, 0);
    } else {
        k_build<<<gE4, 256>>>(ei);
        k_gemm_dual<INDIM, false><<<gGemm, 256>>>(x, W1l, W1r);
    }

    // layer 1 aggregate + epilogue
    k_pull<true, true, false><<<gPull, 256>>>(b1, nullptr);

    // layer 2
    k_gemm_dual<HID, true><<<gGemm, 256>>>(nullptr, W2l, W2r);
    k_pull<false, false, true><<<gPull, 256>>>(b2, out);
}